// round 11
// baseline (speedup 1.0000x reference)
#include <cuda_runtime.h>
#include <cuda_bf16.h>
#include <cstdint>

#define COULOMB_K 14.3996454784936f
#define N_NODES_CAP 500000
#define BLOCK     256

// Packed node table: {charge, sigma} — one 8B gather serves dst's two values.
__device__ float2 g_node[N_NODES_CAP];

// ---------------- prologue: pack table (4 nodes/thread) + zero out ----------------
__global__ void prep_kernel(const float4* __restrict__ charge4,
                            const float4* __restrict__ sigma4,
                            float4* __restrict__ out4, int n4) {
    int i = blockIdx.x * blockDim.x + threadIdx.x;
    if (i >= n4) return;
    float4 c = __ldg(charge4 + i);
    float4 s = __ldg(sigma4 + i);
    float4* tab = reinterpret_cast<float4*>(g_node);   // 2 float2 per float4
    tab[2 * i]     = make_float4(c.x, s.x, c.y, s.y);
    tab[2 * i + 1] = make_float4(c.z, s.z, c.w, s.w);
    out4[i] = make_float4(0.f, 0.f, 0.f, 0.f);
}
__global__ void prep_tail_kernel(const float* __restrict__ charge,
                                 const float* __restrict__ sigma,
                                 float* __restrict__ out, int start, int n) {
    int i = start + threadIdx.x;
    if (i < n) {
        g_node[i] = make_float2(charge[i], sigma[i]);
        out[i] = 0.0f;
    }
}

// full message: K * q_dst * erf(r/(sqrt2*gamma)) * fcut(r) / r
__device__ __forceinline__ void edge_compute(float r, float ss, float2 nd, int d,
                                             float* __restrict__ out) {
    float sd = nd.y;
    float g2  = 2.0f * fmaf(ss, ss, sd * sd);    // 2*(ss^2+sd^2)
    float arg = r * rsqrtf(g2);                  // r / (sqrt2*gamma)
    float x = r * 0.2f;                          // r / CUTOFF
    float p = fmaf(-6.0f, x, 15.0f);
    p = fmaf(p, x, -10.0f);
    float fcut = fmaf(x * x * x, p, 1.0f);       // 1 -10x^3 +15x^4 -6x^5
    fcut = (r <= 5.0f) ? fcut : 0.0f;
    float t = nd.x * erff(arg) * fcut * __fdividef(COULOMB_K, r);
    atomicAdd(out + d, t);                       // RED (no return)
}

// 8 edges/thread: vector streams -> 16 batched gathers -> compute+RED
__global__ void __launch_bounds__(BLOCK)
edge_kernel(const float* __restrict__ bond,
            const int*   __restrict__ src,
            const int*   __restrict__ dst,
            float*       __restrict__ out,
            int n8) {
    int t = blockIdx.x * BLOCK + threadIdx.x;
    if (t >= n8) return;
    long base = (long)t * 2;   // in float4 groups

    const float4* bond4 = reinterpret_cast<const float4*>(bond);
    const int4*   src4  = reinterpret_cast<const int4*>(src);
    const int4*   dst4  = reinterpret_cast<const int4*>(dst);

    // streaming loads, evict-first (keep L1 for the table gathers)
    float4 rA = __ldcs(bond4 + base);
    float4 rB = __ldcs(bond4 + base + 1);
    int4   sA = __ldcs(src4 + base);
    int4   sB = __ldcs(src4 + base + 1);
    int4   dA = __ldcs(dst4 + base);
    int4   dB = __ldcs(dst4 + base + 1);

    // 16 scattered gathers issued contiguously (MLP over L2 latency)
    float ss0 = __ldg(&g_node[sA.x].y), ss1 = __ldg(&g_node[sA.y].y);
    float ss2 = __ldg(&g_node[sA.z].y), ss3 = __ldg(&g_node[sA.w].y);
    float ss4 = __ldg(&g_node[sB.x].y), ss5 = __ldg(&g_node[sB.y].y);
    float ss6 = __ldg(&g_node[sB.z].y), ss7 = __ldg(&g_node[sB.w].y);
    float2 nd0 = __ldg(&g_node[dA.x]), nd1 = __ldg(&g_node[dA.y]);
    float2 nd2 = __ldg(&g_node[dA.z]), nd3 = __ldg(&g_node[dA.w]);
    float2 nd4 = __ldg(&g_node[dB.x]), nd5 = __ldg(&g_node[dB.y]);
    float2 nd6 = __ldg(&g_node[dB.z]), nd7 = __ldg(&g_node[dB.w]);

    edge_compute(rA.x, ss0, nd0, dA.x, out);
    edge_compute(rA.y, ss1, nd1, dA.y, out);
    edge_compute(rA.z, ss2, nd2, dA.z, out);
    edge_compute(rA.w, ss3, nd3, dA.w, out);
    edge_compute(rB.x, ss4, nd4, dB.x, out);
    edge_compute(rB.y, ss5, nd5, dB.y, out);
    edge_compute(rB.z, ss6, nd6, dB.z, out);
    edge_compute(rB.w, ss7, nd7, dB.w, out);
}

__global__ void edge_tail_kernel(const float* __restrict__ bond,
                                 const int*   __restrict__ src,
                                 const int*   __restrict__ dst,
                                 float*       __restrict__ out,
                                 int start, int n_edges) {
    int e = start + blockIdx.x * blockDim.x + threadIdx.x;
    if (e < n_edges) {
        float  ss = __ldg(&g_node[src[e]].y);
        float2 nd = __ldg(&g_node[dst[e]]);
        edge_compute(bond[e], ss, nd, dst[e], out);
    }
}

extern "C" void kernel_launch(void* const* d_in, const int* in_sizes, int n_in,
                              void* d_out, int out_size) {
    const float* charge    = (const float*)d_in[0];
    const float* sigma     = (const float*)d_in[1];
    const float* bond_dist = (const float*)d_in[2];
    const int*   src       = (const int*)d_in[3];
    const int*   dst       = (const int*)d_in[4];
    float* out = (float*)d_out;

    int n_nodes = in_sizes[0];
    int n_edges = in_sizes[2];

    // prologue: pack {charge, sigma} table + zero output
    int nn4 = n_nodes / 4;
    prep_kernel<<<(nn4 + BLOCK - 1) / BLOCK, BLOCK>>>(
        reinterpret_cast<const float4*>(charge),
        reinterpret_cast<const float4*>(sigma),
        reinterpret_cast<float4*>(out), nn4);
    if (nn4 * 4 < n_nodes)
        prep_tail_kernel<<<1, 256>>>(charge, sigma, out, nn4 * 4, n_nodes);

    // edge accumulation (wavefront-pinned flat kernel, measured-optimal form)
    int n8 = n_edges / 8;
    if (n8 > 0) {
        int blocks = (n8 + BLOCK - 1) / BLOCK;
        edge_kernel<<<blocks, BLOCK>>>(bond_dist, src, dst, out, n8);
    }
    if (n8 * 8 < n_edges) {
        int tail = n_edges - n8 * 8;
        edge_tail_kernel<<<(tail + BLOCK - 1) / BLOCK, BLOCK>>>(
            bond_dist, src, dst, out, n8 * 8, n_edges);
    }
}